// round 16
// baseline (speedup 1.0000x reference)
#include <cuda_runtime.h>
#include <cuda_fp16.h>
#include <cstdint>

#define EPS_BN 1e-5f
#define SCALE_ATTN 0.125f
#define CDIM 512
#define MROWS 8192   // B*N

// ============================ scratch (static device mem) ============================
__device__ __align__(16) __half g_xf[MROWS*CDIM];
__device__ __align__(16) __half g_attf[MROWS*CDIM];
__device__ __align__(16) __half g_wq[CDIM*CDIM], g_wk[CDIM*CDIM];
__device__ __align__(16) __half g_wv[CDIM*CDIM], g_wp[CDIM*CDIM];
__device__ float g_bq[CDIM], g_bk[CDIM], g_bv[CDIM], g_bp[CDIM];
__device__ __align__(16) __half g_q[MROWS*CDIM];                 // [row][C] normal
__device__ __align__(16) __half g_kT[MROWS*CDIM], g_vT[MROWS*CDIM]; // [bh][d][n=1024] transposed
__device__ __align__(16) __half g_mh[64*64*64];   // M^T per head fp16, SCALE applied: [bh][e][d]

// ============================ portable PTX helpers ============================
__device__ __forceinline__ uint32_t smem_u32(const void* p) {
    uint32_t a;
    asm("{ .reg .u64 t; cvta.to.shared.u64 t, %1; cvt.u32.u64 %0, t; }" : "=r"(a) : "l"(p));
    return a;
}
__device__ __forceinline__ void cp16(uint32_t saddr, const void* g) {
    asm volatile("cp.async.cg.shared.global [%0], [%1], 16;" :: "r"(saddr), "l"(g) : "memory");
}
__device__ __forceinline__ void cp_commit() {
    asm volatile("cp.async.commit_group;" ::: "memory");
}
template <int N> __device__ __forceinline__ void cp_wait() {
    asm volatile("cp.async.wait_group %0;" :: "n"(N) : "memory");
}
__device__ __forceinline__ void ldsm4(uint32_t* r, uint32_t addr) {
    asm volatile("ldmatrix.sync.aligned.m8n8.x4.shared.b16 {%0,%1,%2,%3}, [%4];"
                 : "=r"(r[0]), "=r"(r[1]), "=r"(r[2]), "=r"(r[3]) : "r"(addr));
}
__device__ __forceinline__ void mma_f16(float* c, const uint32_t* a, uint32_t b0, uint32_t b1) {
    asm volatile(
        "mma.sync.aligned.m16n8k16.row.col.f32.f16.f16.f32 "
        "{%0,%1,%2,%3}, {%4,%5,%6,%7}, {%8,%9}, {%0,%1,%2,%3};"
        : "+f"(c[0]), "+f"(c[1]), "+f"(c[2]), "+f"(c[3])
        : "r"(a[0]), "r"(a[1]), "r"(a[2]), "r"(a[3]), "r"(b0), "r"(b1));
}

// ============================ prep: BN-fold (ILP4) + x->fp16 (ILP4) ============================
__global__ void prep_all(
    const float* __restrict__ x,
    const float* __restrict__ w0, const float* __restrict__ b0, const float* __restrict__ g0,
    const float* __restrict__ be0, const float* __restrict__ mu0, const float* __restrict__ va0,
    const float* __restrict__ w1, const float* __restrict__ b1, const float* __restrict__ g1,
    const float* __restrict__ be1, const float* __restrict__ mu1, const float* __restrict__ va1,
    const float* __restrict__ w2, const float* __restrict__ b2, const float* __restrict__ g2,
    const float* __restrict__ be2, const float* __restrict__ mu2, const float* __restrict__ va2,
    const float* __restrict__ w3, const float* __restrict__ b3, const float* __restrict__ g3,
    const float* __restrict__ be3, const float* __restrict__ mu3, const float* __restrict__ va3)
{
    int tid = threadIdx.x;
    if (blockIdx.x < 256) {
        int base = blockIdx.x * 256 + tid;      // [0, 65536)
#pragma unroll
        for (int u = 0; u < 4; ++u) {
            int idx = base + u * 65536;
            int s = idx >> 16;
            int i4 = idx & 65535;
            const float *w, *b, *g, *beta, *mu, *var;
            __half* wf; float* bias;
            if (s == 0) { w=w0;b=b0;g=g0;beta=be0;mu=mu0;var=va0; wf=g_wq;bias=g_bq; }
            else if (s == 1) { w=w1;b=b1;g=g1;beta=be1;mu=mu1;var=va1; wf=g_wk;bias=g_bk; }
            else if (s == 2) { w=w2;b=b2;g=g2;beta=be2;mu=mu2;var=va2; wf=g_wv;bias=g_bv; }
            else { w=w3;b=b3;g=g3;beta=be3;mu=mu3;var=va3; wf=g_wp;bias=g_bp; }
            int i = i4 * 4;
            int d = i >> 9;
            float sc = g[d] * rsqrtf(var[d] + EPS_BN);
            float4 wv = ((const float4*)w)[i4];
            __half2 h0, h1;
            h0.x = __float2half_rn(wv.x * sc); h0.y = __float2half_rn(wv.y * sc);
            h1.x = __float2half_rn(wv.z * sc); h1.y = __float2half_rn(wv.w * sc);
            ((__half2*)wf)[i4 * 2 + 0] = h0;
            ((__half2*)wf)[i4 * 2 + 1] = h1;
            if ((i & 511) == 0) bias[d] = (b[d] - mu[d]) * sc + beta[d];
        }
    } else {
        int base = (blockIdx.x - 256) * 256 + tid;   // [0, 262144)
#pragma unroll
        for (int u = 0; u < 4; ++u) {
            int i = base + u * 262144;
            float4 v = ((const float4*)x)[i];
            __half2 a; a.x = __float2half_rn(v.x); a.y = __float2half_rn(v.y);
            __half2 b; b.x = __float2half_rn(v.z); b.y = __float2half_rn(v.w);
            ((__half2*)g_xf)[i * 2 + 0] = a;
            ((__half2*)g_xf)[i * 2 + 1] = b;
        }
    }
}

// ============================ HMMA GEMM (fp16, 1-product, BK=64, 3-stage) ============================
// mode 0: fused QKV from xf. sel 0 -> g_q normal; sel 1/2 -> g_kT/g_vT transposed.
// mode 1: P from attf -> fp32 d_out.
#define BK 64
#define NSTAGE (CDIM / BK)          // 8
#define RPITCH 144                  // 128B data + 16B pad
#define T_TB (128 * RPITCH)         // 18432 per operand tile
#define STAGEB (2 * T_TB)           // 36864: [Af, Wf]
#define GEMM_SMEM (3 * STAGEB)      // 110592, x2 CTAs = 221184 <= 228KB

__global__ __launch_bounds__(256, 2)
void gemm_tc(float* __restrict__ Cext, int mode)
{
    extern __shared__ char smem[];
    const __half *Af, *Wf;
    const float* bias;
    int sel = 0, bn;
    if (mode == 0) {
        sel = blockIdx.x >> 2;              // 0=q, 1=k, 2=v
        bn = (blockIdx.x & 3) * 128;
        Af = g_xf;
        Wf = (sel == 0) ? g_wq : (sel == 1) ? g_wk : g_wv;
        bias = (sel == 0) ? g_bq : (sel == 1) ? g_bk : g_bv;
    } else {
        bn = blockIdx.x * 128;
        Af = g_attf;
        Wf = g_wp; bias = g_bp;
    }
    const int bm = blockIdx.y * 128;

    const uint32_t sb = smem_u32(smem);
    const int tid = threadIdx.x;
    const int wid = tid >> 5, lane = tid & 31;
    const int wm = wid & 1, wn = wid >> 1;   // 2(m) x 4(n), 64x32 per warp

    const __half* srcA = Af + (size_t)bm * CDIM;
    const __half* srcW = Wf + (size_t)bn * CDIM;

    auto load_stage = [&](int s, int buf) {
        uint32_t sbase = sb + buf * STAGEB;
        int kof = s * BK;
#pragma unroll
        for (int t = 0; t < 8; ++t) {
            int idx = tid + t * 256;
            int ten = idx >> 10;
            int v = idx & 1023;
            int row = v >> 3, ch = v & 7;
            const __half* g = (ten == 0 ? srcA : srcW) + (size_t)row * CDIM + kof + ch * 8;
            cp16(sbase + ten * T_TB + row * RPITCH + ch * 16, g);
        }
        cp_commit();
    };

    float acc[4][4][4];
#pragma unroll
    for (int i = 0; i < 4; ++i)
#pragma unroll
        for (int j = 0; j < 4; ++j)
#pragma unroll
            for (int k = 0; k < 4; ++k) acc[i][j][k] = 0.f;

    const int g8 = lane >> 3, l8 = lane & 7;
    const int a_row = (g8 & 1) * 8 + l8;
    const int a_k = (g8 >> 1) * 8;
    const int w_row = (g8 >> 1) * 8 + l8;
    const int w_k = (g8 & 1) * 8;

    const uint32_t aoffL = (wm * 64 + a_row) * RPITCH + a_k * 2;
    const uint32_t woffL = (wn * 32 + w_row) * RPITCH + w_k * 2;

    load_stage(0, 0);
    load_stage(1, 1);

    for (int s = 0; s < NSTAGE; ++s) {
        if (s + 1 < NSTAGE) cp_wait<1>(); else cp_wait<0>();
        __syncthreads();                      // all warps done with buf (s+2)%3 (used at stage s-1)
        if (s + 2 < NSTAGE) load_stage(s + 2, (s + 2) % 3);

        const uint32_t base = sb + (s % 3) * STAGEB;
        const uint32_t aB = base + aoffL;
        const uint32_t wB = base + T_TB + woffL;

#pragma unroll
        for (int kk = 0; kk < BK; kk += 16) {
            uint32_t whf[2][4];
            ldsm4(whf[0], wB + kk * 2);
            ldsm4(whf[1], wB + 16 * RPITCH + kk * 2);
            uint32_t ahf[2][4];
            ldsm4(ahf[0], aB + kk * 2);
#pragma unroll
            for (int mi = 0; mi < 4; ++mi) {
                const int cur = mi & 1;
                if (mi < 3) ldsm4(ahf[cur ^ 1], aB + (mi + 1) * (16 * RPITCH) + kk * 2);
#pragma unroll
                for (int nj = 0; nj < 4; ++nj)
                    mma_f16(acc[mi][nj], ahf[cur], whf[nj >> 1][(nj & 1) * 2], whf[nj >> 1][(nj & 1) * 2 + 1]);
            }
        }
    }

    const int r_in = lane >> 2;
    const int c_in = (lane & 3) * 2;
#pragma unroll
    for (int mi = 0; mi < 4; ++mi) {
        int r0 = bm + wm * 64 + mi * 16 + r_in;
#pragma unroll
        for (int nj = 0; nj < 4; ++nj) {
            int c0 = bn + wn * 32 + nj * 8 + c_in;
            float b0 = bias[c0], b1 = bias[c0 + 1];
            float v00 = fmaxf(acc[mi][nj][0] + b0, 0.f);
            float v01 = fmaxf(acc[mi][nj][1] + b1, 0.f);
            float v10 = fmaxf(acc[mi][nj][2] + b0, 0.f);
            float v11 = fmaxf(acc[mi][nj][3] + b1, 0.f);
            if (mode == 1) {
                float2 lo = {v00, v01};
                float2 hi = {v10, v11};
                *(float2*)(Cext + (size_t)r0 * CDIM + c0) = lo;
                *(float2*)(Cext + (size_t)(r0 + 8) * CDIM + c0) = hi;
            } else if (sel == 0) {
                __half2 lo; lo.x = __float2half_rn(v00); lo.y = __float2half_rn(v01);
                __half2 hi; hi.x = __float2half_rn(v10); hi.y = __float2half_rn(v11);
                *(__half2*)(g_q + (size_t)r0 * CDIM + c0) = lo;
                *(__half2*)(g_q + (size_t)(r0 + 8) * CDIM + c0) = hi;
            } else {
                __half* T = (sel == 1) ? g_kT : g_vT;
                int b_ = r0 >> 10, n_ = r0 & 1023;
                int hh = c0 >> 6, dd = c0 & 63;
                size_t rowb = ((size_t)(b_ * 8 + hh) * 64 + dd) * 1024;
                T[rowb + n_] = __float2half_rn(v00);
                T[rowb + 1024 + n_] = __float2half_rn(v01);
                T[rowb + n_ + 8] = __float2half_rn(v10);
                T[rowb + 1024 + n_ + 8] = __float2half_rn(v11);
            }
        }
    }
}

// ============================ kv via tensor cores -> M^T fp16 (SCALE applied) ============================
#define KV_PITCH 272                 // 128 fp16 = 256B + 16 pad
#define KV_TB (64 * KV_PITCH)        // 17408 per tensor per chunk
#define KV_STG (2 * KV_TB)           // 34816: [vT, kT]
#define KV_SMEM (2 * KV_STG)         // 69632

__global__ __launch_bounds__(128)
void kv_tc()
{
    extern __shared__ char smem[];
    int bh = blockIdx.x;
    int tid = threadIdx.x;
    int wid = tid >> 5, lane = tid & 31;

    const uint32_t sb = smem_u32(smem);
    const __half* vsrc = g_vT + (size_t)bh * 64 * 1024;
    const __half* ksrc = g_kT + (size_t)bh * 64 * 1024;

    auto load_chunk = [&](int c, int buf) {
        uint32_t sbase = sb + buf * KV_STG;
        int n0 = c * 128;
#pragma unroll
        for (int t = 0; t < 16; ++t) {
            int idx = tid + t * 128;
            int ten = idx >> 10;              // 0=vT 1=kT
            int v = idx & 1023;
            int row = v >> 4, ch = v & 15;
            const __half* g = (ten == 0 ? vsrc : ksrc) + (size_t)row * 1024 + n0 + ch * 8;
            cp16(sbase + ten * KV_TB + row * KV_PITCH + ch * 16, g);
        }
        cp_commit();
    };

    float acc[8][4];
#pragma unroll
    for (int j = 0; j < 8; ++j)
#pragma unroll
        for (int k = 0; k < 4; ++k) acc[j][k] = 0.f;

    const int g8 = lane >> 3, l8 = lane & 7;
    const int a_row = (g8 & 1) * 8 + l8;
    const int a_k = (g8 >> 1) * 8;
    const int w_row = (g8 >> 1) * 8 + l8;
    const int w_k = (g8 & 1) * 8;

    const uint32_t aoffL = (wid * 16 + a_row) * KV_PITCH + a_k * 2;   // A = vT, warp e-tile
    const uint32_t woffL = w_row * KV_PITCH + w_k * 2;                // B = kT

    load_chunk(0, 0);

    for (int c = 0; c < 8; ++c) {
        cp_wait<0>();
        __syncthreads();
        if (c + 1 < 8) load_chunk(c + 1, (c + 1) & 1);

        const uint32_t base = sb + (c & 1) * KV_STG;
        const uint32_t aB = base + aoffL;
        const uint32_t wB = base + KV_TB + woffL;

#pragma unroll
        for (int kk = 0; kk < 128; kk += 16) {
            uint32_t bf[4][4];
#pragma unroll
            for (int j = 0; j < 4; ++j)
                ldsm4(bf[j], wB + j * (16 * KV_PITCH) + kk * 2);
            uint32_t af[4];
            ldsm4(af, aB + kk * 2);
#pragma unroll
            for (int nj = 0; nj < 8; ++nj)
                mma_f16(acc[nj], af, bf[nj >> 1][(nj & 1) * 2], bf[nj >> 1][(nj & 1) * 2 + 1]);
        }
    }

    const int r_in = lane >> 2;
    const int c_in = (lane & 3) * 2;
    __half* mdst = g_mh + (size_t)bh * 4096;
#pragma unroll
    for (int nj = 0; nj < 8; ++nj) {
        int e0 = wid * 16 + r_in;
        int d0 = nj * 8 + c_in;
        __half2 lo, hi;
        lo.x = __float2half_rn(acc[nj][0] * SCALE_ATTN);
        lo.y = __float2half_rn(acc[nj][1] * SCALE_ATTN);
        hi.x = __float2half_rn(acc[nj][2] * SCALE_ATTN);
        hi.y = __float2half_rn(acc[nj][3] * SCALE_ATTN);
        *(__half2*)(mdst + e0 * 64 + d0) = lo;
        *(__half2*)(mdst + (e0 + 8) * 64 + d0) = hi;
    }
}

// ============================ qm via tensor cores: att = relu(q @ M) -> fp16 ============================
#define QM_QPITCH 144
#define QM_Q_TB (128 * QM_QPITCH)   // 18432

__global__ __launch_bounds__(128)
void qm_tc()
{
    __shared__ __align__(16) char qs[QM_Q_TB];
    __shared__ __align__(16) char ms[64 * QM_QPITCH];

    int nt = blockIdx.x;   // 0..7 (128-row tiles)
    int h = blockIdx.y, b = blockIdx.z;
    int bh = b * 8 + h;
    int tid = threadIdx.x;
    int wid = tid >> 5, lane = tid & 31;

    const uint32_t qB0 = smem_u32(qs);
    const uint32_t mB0 = smem_u32(ms);

    const __half* qbase = g_q + ((size_t)(b * 1024 + nt * 128)) * CDIM + h * 64;
#pragma unroll
    for (int t = 0; t < 8; ++t) {
        int idx = tid + t * 128;
        int row = idx >> 3, ch = idx & 7;
        cp16(qB0 + row * QM_QPITCH + ch * 16, qbase + (size_t)row * CDIM + ch * 8);
    }
    // M fp16: 64 rows x 8 chunks = 512 cp16, 4/thread
    const __half* mbase = g_mh + (size_t)bh * 4096;
#pragma unroll
    for (int t = 0; t < 4; ++t) {
        int idx = tid + t * 128;
        int row = idx >> 3, ch = idx & 7;
        cp16(mB0 + row * QM_QPITCH + ch * 16, mbase + (size_t)row * 64 + ch * 8);
    }
    cp_commit();
    cp_wait<0>();
    __syncthreads();

    const int g8 = lane >> 3, l8 = lane & 7;
    const int a_row = (g8 & 1) * 8 + l8;
    const int a_k = (g8 >> 1) * 8;
    const int w_row = (g8 >> 1) * 8 + l8;
    const int w_k = (g8 & 1) * 8;

    const uint32_t aB = qB0 + (wid * 32 + a_row) * QM_QPITCH + a_k * 2;
    const uint32_t wB = mB0 + w_row * QM_QPITCH + w_k * 2;

    float acc[2][8][4];
#pragma unroll
    for (int i = 0; i < 2; ++i)
#pragma unroll
        for (int j = 0; j < 8; ++j)
#pragma unroll
            for (int k = 0; k < 4; ++k) acc[i][j][k] = 0.f;

#pragma unroll
    for (int kk = 0; kk < 64; kk += 16) {
        uint32_t bf[4][4];
#pragma unroll
        for (int j = 0; j < 4; ++j)
            ldsm4(bf[j], wB + j * (16 * QM_QPITCH) + kk * 2);
        uint32_t af[2][4];
        ldsm4(af[0], aB + kk * 2);
        ldsm4(af[1], aB + 16 * QM_QPITCH + kk * 2);
#pragma unroll
        for (int mi = 0; mi < 2; ++mi)
#pragma unroll
            for (int nj = 0; nj < 8; ++nj)
                mma_f16(acc[mi][nj], af[mi], bf[nj >> 1][(nj & 1) * 2], bf[nj >> 1][(nj & 1) * 2 + 1]);
    }

    const int r_in = lane >> 2;
    const int c_in = (lane & 3) * 2;
#pragma unroll
    for (int mi = 0; mi < 2; ++mi) {
        size_t r0 = (size_t)(b * 1024 + nt * 128 + wid * 32 + mi * 16 + r_in);
#pragma unroll
        for (int nj = 0; nj < 8; ++nj) {
            int c0 = h * 64 + nj * 8 + c_in;
            __half2 lo, hi;
            lo.x = __float2half_rn(fmaxf(acc[mi][nj][0], 0.f));
            lo.y = __float2half_rn(fmaxf(acc[mi][nj][1], 0.f));
            hi.x = __float2half_rn(fmaxf(acc[mi][nj][2], 0.f));
            hi.y = __float2half_rn(fmaxf(acc[mi][nj][3], 0.f));
            *(__half2*)(g_attf + r0 * CDIM + c0) = lo;
            *(__half2*)(g_attf + (r0 + 8) * CDIM + c0) = hi;
        }
    }
}

// ============================ host launch ============================
extern "C" void kernel_launch(void* const* d_in, const int* in_sizes, int n_in,
                              void* d_out, int out_size)
{
    (void)in_sizes; (void)n_in; (void)out_size;
    const float* x = (const float*)d_in[0];
    const float** p = (const float**)(d_in + 1);   // 24 params: 4 sets x 6

    cudaFuncSetAttribute(gemm_tc, cudaFuncAttributeMaxDynamicSharedMemorySize, GEMM_SMEM);
    cudaFuncSetAttribute(kv_tc, cudaFuncAttributeMaxDynamicSharedMemorySize, KV_SMEM);

    prep_all<<<1280, 256>>>(x,
        p[0], p[1], p[2], p[3], p[4], p[5],
        p[6], p[7], p[8], p[9], p[10], p[11],
        p[12], p[13], p[14], p[15], p[16], p[17],
        p[18], p[19], p[20], p[21], p[22], p[23]);

    // fused QKV: grid (12, 64) = 768 CTAs
    gemm_tc<<<dim3(12, 64), 256, GEMM_SMEM>>>(nullptr, 0);

    kv_tc<<<64, 128, KV_SMEM>>>();
    qm_tc<<<dim3(8, 8, 8), 128>>>();

    // P projection
    gemm_tc<<<dim3(4, 64), 256, GEMM_SMEM>>>((float*)d_out, 1);
}